// round 12
// baseline (speedup 1.0000x reference)
#include <cuda_runtime.h>
#include <cstdint>
#include <math_constants.h>

#define N_NODES  20000
#define N_EDGES  160000
#define N_GRAPHS 100

// ---------------- scratch (device globals; no allocation allowed) ----------------
__device__ float g_bufA[N_NODES * 1024];
__device__ float g_bufB[N_NODES * 1024];
__device__ float g_bufC[N_NODES * 1024];
__device__ float g_bufD[N_NODES * 1024];
__device__ int   g_deg[N_NODES];
__device__ int   g_work[N_NODES];
__device__ int   g_ptr[N_NODES + 1];
__device__ int   g_eid[N_EDGES];
__device__ int   g_esrc[N_EDGES];
__device__ int   g_ptr2[N_NODES + 1];
__device__ int   g_eid2[N_EDGES];
__device__ int   g_esrc2[N_EDGES];
__device__ int   g_last[N_GRAPHS];

// ================= tensor-core GEMM (mma.sync m16n8k8 tf32, 3-term split) ==========
__device__ __forceinline__ float tf32f(float x) {
    uint32_t u;
    asm("cvt.rna.tf32.f32 %0, %1;" : "=r"(u) : "f"(x));
    return __uint_as_float(u);
}
__device__ __forceinline__ void mma_tf32(float* d, const uint32_t* a, const uint32_t* b) {
    asm volatile("mma.sync.aligned.m16n8k8.row.col.f32.tf32.tf32.f32 "
                 "{%0,%1,%2,%3}, {%4,%5,%6,%7}, {%8,%9}, {%0,%1,%2,%3};"
                 : "+f"(d[0]), "+f"(d[1]), "+f"(d[2]), "+f"(d[3])
                 : "r"(a[0]), "r"(a[1]), "r"(a[2]), "r"(a[3]), "r"(b[0]), "r"(b[1]));
}
__device__ __forceinline__ uint32_t smem_u32(const void* p) {
    uint32_t a;
    asm("{ .reg .u64 t; cvta.to.shared.u64 t, %1; cvt.u32.u64 %0, t; }" : "=r"(a) : "l"(p));
    return a;
}
#define CP_ASYNC16(dst, src, pb) \
    asm volatile("cp.async.cg.shared.global [%0], [%1], 16, %2;" :: "r"(dst), "l"(src), "r"(pb))
#define CP_COMMIT() asm volatile("cp.async.commit_group;" ::: "memory")

#define STAGE_F 8192
#define GEMM_STAGES 3
#define GEMM_SMEM (GEMM_STAGES * STAGE_F * 4)   // 96 KB

__global__ void __launch_bounds__(256, 2)
gemm_mma_kernel(const float* __restrict__ A,
                const float* __restrict__ B0, const float* __restrict__ B1,
                float* __restrict__ C0, float* __restrict__ C1,
                int M, int N, int K) {
    extern __shared__ __align__(16) float smem[];
    const uint32_t sb = smem_u32(smem);
    const float* B = blockIdx.z ? B1 : B0;
    float* C = blockIdx.z ? C1 : C0;
    const int bm = blockIdx.y * 128;
    const int bn = blockIdx.x * 128;
    const int tid = threadIdx.x, warp = tid >> 5, lane = tid & 31;
    const int wm = warp >> 2, wn = warp & 3;   // warp tile 64(m) x 32(n)

    float c[4][4][4];
#pragma unroll
    for (int i = 0; i < 4; i++)
#pragma unroll
        for (int j = 0; j < 4; j++)
#pragma unroll
            for (int r = 0; r < 4; r++) c[i][j][r] = 0.f;

    const int T = K / 32;

    auto issue_stage = [&](int t) {
        const uint32_t stg = sb + (t % GEMM_STAGES) * STAGE_F * 4;
        const int k0 = t * 32;
#pragma unroll
        for (int i = 0; i < 4; i++) {
            const int v = tid + i * 256;
            const int row = v >> 3, kq4 = v & 7;
            const int kt = kq4 >> 1;
            const int rg = ((kq4 & 1) << 1) | ((row & 8) >> 3);
            const int mtg = (row >> 4) & 7;
            const int lnb = (((row & 7) << 2) ^ (kt << 3)) ^ (rg << 2);
            const int offA = ((kt * 8 + mtg) * 4 + rg) * 32 + lnb;
            const float* src = &A[(size_t)(bm + row) * K + k0 + kq4 * 4];
            CP_ASYNC16(stg + offA * 4, src, (bm + row < M) ? 16 : 0);
        }
#pragma unroll
        for (int i = 0; i < 4; i++) {
            const int v = tid + i * 256;
            const int kq = v >> 5, n4 = (v & 31) * 4;
            const int offB = 4096 + kq * 128 + (n4 ^ ((kq & 3) << 3));
            const float* src = &B[(size_t)(k0 + kq) * N + bn + n4];
            CP_ASYNC16(stg + offB * 4, src, 16);
        }
        CP_COMMIT();
    };

    issue_stage(0);
    if (T > 1) issue_stage(1);

    const int xorn = (lane & 3) << 3;
    const int g = lane >> 2, tq = lane & 3;

    for (int t = 0; t < T; t++) {
        if (t + 1 < T) asm volatile("cp.async.wait_group 1;" ::: "memory");
        else           asm volatile("cp.async.wait_group 0;" ::: "memory");
        __syncthreads();
        const float* s = smem + (t % GEMM_STAGES) * STAGE_F;
#pragma unroll
        for (int kt = 0; kt < 4; kt++) {
            uint32_t bh[4][2], bl[4][2];
#pragma unroll
            for (int nt = 0; nt < 4; nt++) {
                const int nl = wn * 32 + nt * 8 + g;
#pragma unroll
                for (int r = 0; r < 2; r++) {
                    const int k = kt * 8 + tq + r * 4;
                    const float v = s[4096 + k * 128 + (nl ^ xorn)];
                    const float h = tf32f(v);
                    bh[nt][r] = __float_as_uint(h);
                    bl[nt][r] = __float_as_uint(v - h);
                }
            }
#pragma unroll
            for (int mt = 0; mt < 4; mt++) {
                const int mtg = wm * 4 + mt;
                uint32_t ah[4], al[4];
#pragma unroll
                for (int r = 0; r < 4; r++) {
                    const int lnp = (lane ^ (kt * 8)) ^ (r * 4);
                    const float v = s[((kt * 8 + mtg) * 4 + r) * 32 + lnp];
                    const float h = tf32f(v);
                    ah[r] = __float_as_uint(h);
                    al[r] = __float_as_uint(v - h);
                }
#pragma unroll
                for (int nt = 0; nt < 4; nt++) {
                    mma_tf32(c[mt][nt], ah, bh[nt]);
                    mma_tf32(c[mt][nt], ah, bl[nt]);
                    mma_tf32(c[mt][nt], al, bh[nt]);
                }
            }
        }
        if (t + 2 < T) issue_stage(t + 2);
    }

#pragma unroll
    for (int mt = 0; mt < 4; mt++) {
        const int r0 = bm + wm * 64 + mt * 16 + g;
#pragma unroll
        for (int nt = 0; nt < 4; nt++) {
            const int col = bn + wn * 32 + nt * 8 + tq * 2;
            if (r0 < M)
                *reinterpret_cast<float2*>(&C[(size_t)r0 * N + col]) =
                    make_float2(c[mt][nt][0], c[mt][nt][1]);
            if (r0 + 8 < M)
                *reinterpret_cast<float2*>(&C[(size_t)(r0 + 8) * N + col]) =
                    make_float2(c[mt][nt][2], c[mt][nt][3]);
        }
    }
}

// ---------------- CSR build ----------------
__global__ void zero_int_kernel(int* p, int n) {
    int i = blockIdx.x * blockDim.x + threadIdx.x;
    if (i < n) p[i] = 0;
}
__global__ void degree_kernel(const int* __restrict__ dst, int* __restrict__ deg, int E) {
    int i = blockIdx.x * blockDim.x + threadIdx.x;
    if (i < E) atomicAdd(&deg[dst[i]], 1);
}
__global__ void scan_kernel(const int* __restrict__ deg, int* __restrict__ ptr,
                            int* __restrict__ work, int n) {
    __shared__ int sm[1024];
    const int tid = threadIdx.x;
    const int chunk = (n + 1023) >> 10;
    const int start = tid * chunk;
    const int end = min(start + chunk, n);
    int s = 0;
    for (int i = start; i < end; i++) s += deg[i];
    sm[tid] = s;
    __syncthreads();
    for (int off = 1; off < 1024; off <<= 1) {
        int v = (tid >= off) ? sm[tid - off] : 0;
        __syncthreads();
        sm[tid] += v;
        __syncthreads();
    }
    int excl = (tid == 0) ? 0 : sm[tid - 1];
    for (int i = start; i < end; i++) {
        ptr[i] = excl;
        work[i] = excl;
        excl += deg[i];
    }
    if (tid == 0) ptr[n] = sm[1023];
}
__global__ void scatter_kernel(const int* __restrict__ src, const int* __restrict__ dst,
                               int* __restrict__ work, int* __restrict__ eid,
                               int* __restrict__ esrc, int E) {
    int e = blockIdx.x * blockDim.x + threadIdx.x;
    if (e < E) {
        int p = atomicAdd(&work[dst[e]], 1);
        eid[p] = e;
        esrc[p] = src[e];
    }
}

// ---------------- fused single-pass attention, head-split + edge pipeline ----------
// HW = heads per warp; blockIdx.y = head group. Online softmax in registers; the
// edge loop prefetches next edge's src row + edge attrs while computing current.
template <int H, int C, int HW, bool EA, bool RELU>
__global__ void __launch_bounds__(256, 2)
node_attn_kernel(const float* __restrict__ xl, const float* __restrict__ xr,
                 const float* __restrict__ ea, const float* __restrict__ We,
                 const float* __restrict__ att, const float* __restrict__ bias,
                 const int* __restrict__ ptr, const int* __restrict__ eid,
                 const int* __restrict__ esrc,
                 float* __restrict__ out, int n) {
    constexpr int HC = H * C;
    constexpr int WC = HW * C;          // channels owned by this warp's head group
    constexpr int F4 = WC / 128;        // float4 slots per lane
    __shared__ float s_att[WC];
    __shared__ float s_We[EA ? 8 * WC : 4];
    const int cb = blockIdx.y * WC;     // channel base of this head group
    for (int i = threadIdx.x; i < WC; i += blockDim.x) s_att[i] = att[cb + i];
    if (EA)
        for (int i = threadIdx.x; i < 8 * WC; i += blockDim.x) {
            const int k = i / WC, c = i - k * WC;
            s_We[i] = We[k * HC + cb + c];
        }
    __syncthreads();

    const int warp = threadIdx.x >> 5, lane = threadIdx.x & 31;
    const int d = blockIdx.x * 8 + warp;
    if (d >= n) return;
    const int p0 = ptr[d], p1 = ptr[d + 1];

    int lidx[F4];
#pragma unroll
    for (int j = 0; j < F4; j++) lidx[j] = lane * 4 + j * 128;   // local channel idx

    float4 xrv[F4];
#pragma unroll
    for (int j = 0; j < F4; j++)
        xrv[j] = *reinterpret_cast<const float4*>(xr + (size_t)d * HC + cb + lidx[j]);

    float mxj[F4], denj[F4];
    float4 acc[F4];
#pragma unroll
    for (int j = 0; j < F4; j++) {
        mxj[j] = -CUDART_INF_F;
        denj[j] = 0.f;
        acc[j] = make_float4(0.f, 0.f, 0.f, 0.f);
    }

    // ---- prefetch edge p0 ----
    float4 avN[F4];
    float earN[8];
    if (p0 < p1) {
        const int s = esrc[p0];
        const float* xs = xl + (size_t)s * HC + cb;
#pragma unroll
        for (int j = 0; j < F4; j++)
            avN[j] = *reinterpret_cast<const float4*>(xs + lidx[j]);
        if (EA) {
            const float* er = ea + (size_t)eid[p0] * 8;
#pragma unroll
            for (int k = 0; k < 8; k++) earN[k] = __ldg(er + k);
        }
    }

    for (int p = p0; p < p1; p++) {
        float4 av[F4];
        float earC[8];
#pragma unroll
        for (int j = 0; j < F4; j++) av[j] = avN[j];
        if (EA) {
#pragma unroll
            for (int k = 0; k < 8; k++) earC[k] = earN[k];
        }
        // ---- issue next edge's loads before computing current ----
        if (p + 1 < p1) {
            const int s = esrc[p + 1];
            const float* xs = xl + (size_t)s * HC + cb;
#pragma unroll
            for (int j = 0; j < F4; j++)
                avN[j] = *reinterpret_cast<const float4*>(xs + lidx[j]);
            if (EA) {
                const float* er = ea + (size_t)eid[p + 1] * 8;
#pragma unroll
                for (int k = 0; k < 8; k++) earN[k] = __ldg(er + k);
            }
        }
        // ---- current edge: dot + leaky relu + att ----
        float dotj[F4];
#pragma unroll
        for (int j = 0; j < F4; j++) {
            float vx = av[j].x + xrv[j].x, vy = av[j].y + xrv[j].y;
            float vz = av[j].z + xrv[j].z, vw = av[j].w + xrv[j].w;
            if (EA) {
#pragma unroll
                for (int k = 0; k < 8; k++) {
                    float4 w = *reinterpret_cast<const float4*>(&s_We[k * WC + lidx[j]]);
                    vx += earC[k] * w.x; vy += earC[k] * w.y;
                    vz += earC[k] * w.z; vw += earC[k] * w.w;
                }
            }
            vx = (vx >= 0.f) ? vx : 0.2f * vx;
            vy = (vy >= 0.f) ? vy : 0.2f * vy;
            vz = (vz >= 0.f) ? vz : 0.2f * vz;
            vw = (vw >= 0.f) ? vw : 0.2f * vw;
            float4 t = *reinterpret_cast<const float4*>(&s_att[lidx[j]]);
            dotj[j] = t.x * vx + t.y * vy + t.z * vz + t.w * vw;
        }
        float tj[F4];
        if constexpr (C >= 128) {
            constexpr int JPH = C / 128;
#pragma unroll
            for (int h = 0; h < HW; h++) {
                float sacc = 0.f;
#pragma unroll
                for (int m = 0; m < JPH; m++) sacc += dotj[h * JPH + m];
#pragma unroll
                for (int o = 16; o > 0; o >>= 1) sacc += __shfl_xor_sync(0xffffffffu, sacc, o);
#pragma unroll
                for (int m = 0; m < JPH; m++) tj[h * JPH + m] = sacc;
            }
        } else {   // C == 64: head spans 16 lanes
#pragma unroll
            for (int j = 0; j < F4; j++) {
                float sacc = dotj[j];
#pragma unroll
                for (int o = 8; o > 0; o >>= 1) sacc += __shfl_xor_sync(0xffffffffu, sacc, o);
                tj[j] = sacc;
            }
        }
#pragma unroll
        for (int j = 0; j < F4; j++) {
            const float mn = fmaxf(mxj[j], tj[j]);
            const float so = __expf(mxj[j] - mn);
            const float e  = __expf(tj[j] - mn);
            mxj[j] = mn;
            denj[j] = denj[j] * so + e;
            acc[j].x = acc[j].x * so + e * av[j].x;
            acc[j].y = acc[j].y * so + e * av[j].y;
            acc[j].z = acc[j].z * so + e * av[j].z;
            acc[j].w = acc[j].w * so + e * av[j].w;
        }
    }

#pragma unroll
    for (int j = 0; j < F4; j++) {
        const float inv = 1.f / (denj[j] + 1e-16f);
        float4 b = *reinterpret_cast<const float4*>(bias + cb + lidx[j]);
        float4 o = make_float4(acc[j].x * inv + b.x, acc[j].y * inv + b.y,
                               acc[j].z * inv + b.z, acc[j].w * inv + b.w);
        if (RELU) {
            o.x = fmaxf(o.x, 0.f); o.y = fmaxf(o.y, 0.f);
            o.z = fmaxf(o.z, 0.f); o.w = fmaxf(o.w, 0.f);
        }
        *reinterpret_cast<float4*>(out + (size_t)d * HC + cb + lidx[j]) = o;
    }
}

// ---------------- readout ----------------
__global__ void last_idx_kernel(const int* __restrict__ n_nodes, int* __restrict__ last, int G) {
    if (threadIdx.x == 0 && blockIdx.x == 0) {
        int s = 0;
        for (int i = 0; i < G; i++) { s += n_nodes[i]; last[i] = s - 1; }
    }
}
__global__ void fc_kernel(const float* __restrict__ h, const int* __restrict__ last,
                          const float* __restrict__ W1, const float* __restrict__ b1,
                          const float* __restrict__ W2, const float* __restrict__ b2,
                          float* __restrict__ out) {
    __shared__ float row[384];
    __shared__ float red[64];
    const int g = blockIdx.x, t = threadIdx.x;
    const int node = last[g];
    for (int i = t; i < 384; i += 64) row[i] = h[(size_t)node * 384 + i];
    __syncthreads();
    float acc = b1[t];
    for (int k = 0; k < 384; k++) acc += row[k] * W1[k * 64 + t];
    acc = fmaxf(acc, 0.f);
    red[t] = acc * W2[t];
    __syncthreads();
    if (t < 32) {
        float p = red[t] + red[t + 32];
#pragma unroll
        for (int o = 16; o > 0; o >>= 1) p += __shfl_xor_sync(0xffffffffu, p, o);
        if (t == 0) out[g] = p + b2[0];
    }
}

// ---------------- launch ----------------
extern "C" void kernel_launch(void* const* d_in, const int* in_sizes, int n_in,
                              void* d_out, int out_size) {
    const float* x       = (const float*)d_in[0];
    const float* ea      = (const float*)d_in[1];
    const float* Wl1     = (const float*)d_in[2];
    const float* Wr1     = (const float*)d_in[3];
    const float* We1     = (const float*)d_in[4];
    const float* att1    = (const float*)d_in[5];
    const float* b1      = (const float*)d_in[6];
    const float* Wl2     = (const float*)d_in[7];
    const float* Wr2     = (const float*)d_in[8];
    const float* We2     = (const float*)d_in[9];
    const float* att2    = (const float*)d_in[10];
    const float* b2      = (const float*)d_in[11];
    const float* Wlp     = (const float*)d_in[12];
    const float* Wrp     = (const float*)d_in[13];
    const float* attp    = (const float*)d_in[14];
    const float* bp      = (const float*)d_in[15];
    const float* Wfc1    = (const float*)d_in[16];
    const float* bfc1    = (const float*)d_in[17];
    const float* Wfc2    = (const float*)d_in[18];
    const float* bfc2    = (const float*)d_in[19];
    const int*   ei      = (const int*)d_in[20];
    const int*   eim     = (const int*)d_in[21];
    const int*   n_nodes = (const int*)d_in[22];

    const int N = N_NODES, E = N_EDGES;
    const int* src  = ei;
    const int* dst  = ei + E;
    const int* srcm = eim;
    const int* dstm = eim + E;

    float *bufA, *bufB, *bufC, *bufD;
    int *deg, *work, *ptr, *eid, *esrc, *ptr2, *eid2, *esrc2, *last;
    cudaGetSymbolAddress((void**)&bufA, g_bufA);
    cudaGetSymbolAddress((void**)&bufB, g_bufB);
    cudaGetSymbolAddress((void**)&bufC, g_bufC);
    cudaGetSymbolAddress((void**)&bufD, g_bufD);
    cudaGetSymbolAddress((void**)&deg, g_deg);
    cudaGetSymbolAddress((void**)&work, g_work);
    cudaGetSymbolAddress((void**)&ptr, g_ptr);
    cudaGetSymbolAddress((void**)&eid, g_eid);
    cudaGetSymbolAddress((void**)&esrc, g_esrc);
    cudaGetSymbolAddress((void**)&ptr2, g_ptr2);
    cudaGetSymbolAddress((void**)&eid2, g_eid2);
    cudaGetSymbolAddress((void**)&esrc2, g_esrc2);
    cudaGetSymbolAddress((void**)&last, g_last);

    cudaFuncSetAttribute(gemm_mma_kernel, cudaFuncAttributeMaxDynamicSharedMemorySize, GEMM_SMEM);

    const int MB = (N + 127) / 128;
    const int EB = (E + 255) / 256;
    const int NB = (N + 255) / 256;

    // ===== master CSR (partial) + layer-1 GEMM early =====
    zero_int_kernel<<<NB, 256>>>(deg, N);
    degree_kernel<<<EB, 256>>>(dstm, deg, E);
    scan_kernel<<<1, 1024>>>(deg, ptr2, work, N);
    gemm_mma_kernel<<<dim3(1024 / 128, MB, 2), 256, GEMM_SMEM>>>(x, Wl1, Wr1, bufA, bufB, N, 1024, 64);
    scatter_kernel<<<EB, 256>>>(srcm, dstm, work, eid2, esrc2, E);

    // ===== main CSR =====
    zero_int_kernel<<<NB, 256>>>(deg, N);
    degree_kernel<<<EB, 256>>>(dst, deg, E);
    scan_kernel<<<1, 1024>>>(deg, ptr, work, N);
    scatter_kernel<<<EB, 256>>>(src, dst, work, eid, esrc, E);

    // ===== Layer 1 attention: 1 head/warp, 4 head groups, pipelined =====
    node_attn_kernel<4, 256, 1, true, true><<<dim3((N + 7) / 8, 4), 256>>>(
        bufA, bufB, ea, We1, att1, b1, ptr, eid, esrc, bufC, N);

    // ===== Layer 2 =====
    gemm_mma_kernel<<<dim3(256 / 128, MB, 2), 256, GEMM_SMEM>>>(bufC, Wl2, Wr2, bufA, bufB, N, 256, 1024);
    node_attn_kernel<4, 64, 2, true, true><<<dim3((N + 7) / 8, 2), 256>>>(
        bufA, bufB, ea, We2, att2, b2, ptr, eid, esrc, bufD, N);

    // ===== Layer 3 (master edges) =====
    gemm_mma_kernel<<<dim3(384 / 128, MB, 2), 256, GEMM_SMEM>>>(bufD, Wlp, Wrp, bufA, bufB, N, 384, 256);
    node_attn_kernel<6, 64, 2, false, false><<<dim3((N + 7) / 8, 3), 256>>>(
        bufA, bufB, nullptr, nullptr, attp, bp, ptr2, eid2, esrc2, bufC, N);

    // ===== readout + MLP head =====
    last_idx_kernel<<<1, 32>>>(n_nodes, last, N_GRAPHS);
    fc_kernel<<<N_GRAPHS, 64>>>(bufC, last, Wfc1, bfc1, Wfc2, bfc2, (float*)d_out);
}

// round 13
// speedup vs baseline: 1.0489x; 1.0489x over previous
#include <cuda_runtime.h>
#include <cstdint>
#include <math_constants.h>

#define N_NODES  20000
#define N_EDGES  160000
#define N_GRAPHS 100

// ---------------- scratch (device globals; no allocation allowed) ----------------
__device__ float g_bufA[N_NODES * 1024];
__device__ float g_bufB[N_NODES * 1024];
__device__ float g_bufC[N_NODES * 1024];
__device__ float g_bufD[N_NODES * 1024];
__device__ int   g_deg[N_NODES];
__device__ int   g_work[N_NODES];
__device__ int   g_ptr[N_NODES + 1];
__device__ int   g_eid[N_EDGES];
__device__ int   g_esrc[N_EDGES];
__device__ int   g_ptr2[N_NODES + 1];
__device__ int   g_eid2[N_EDGES];
__device__ int   g_esrc2[N_EDGES];
__device__ int   g_last[N_GRAPHS];

// ================= tensor-core GEMM (mma.sync m16n8k8 tf32, 3-term split) ==========
__device__ __forceinline__ float tf32f(float x) {
    uint32_t u;
    asm("cvt.rna.tf32.f32 %0, %1;" : "=r"(u) : "f"(x));
    return __uint_as_float(u);
}
__device__ __forceinline__ void mma_tf32(float* d, const uint32_t* a, const uint32_t* b) {
    asm volatile("mma.sync.aligned.m16n8k8.row.col.f32.tf32.tf32.f32 "
                 "{%0,%1,%2,%3}, {%4,%5,%6,%7}, {%8,%9}, {%0,%1,%2,%3};"
                 : "+f"(d[0]), "+f"(d[1]), "+f"(d[2]), "+f"(d[3])
                 : "r"(a[0]), "r"(a[1]), "r"(a[2]), "r"(a[3]), "r"(b[0]), "r"(b[1]));
}
__device__ __forceinline__ uint32_t smem_u32(const void* p) {
    uint32_t a;
    asm("{ .reg .u64 t; cvta.to.shared.u64 t, %1; cvt.u32.u64 %0, t; }" : "=r"(a) : "l"(p));
    return a;
}
#define CP_ASYNC16(dst, src, pb) \
    asm volatile("cp.async.cg.shared.global [%0], [%1], 16, %2;" :: "r"(dst), "l"(src), "r"(pb))
#define CP_COMMIT() asm volatile("cp.async.commit_group;" ::: "memory")

#define STAGE_F 8192
#define GEMM_STAGES 3
#define GEMM_SMEM (GEMM_STAGES * STAGE_F * 4)   // 96 KB

__global__ void __launch_bounds__(256, 2)
gemm_mma_kernel(const float* __restrict__ A,
                const float* __restrict__ B0, const float* __restrict__ B1,
                float* __restrict__ C0, float* __restrict__ C1,
                int M, int N, int K) {
    extern __shared__ __align__(16) float smem[];
    const uint32_t sb = smem_u32(smem);
    const float* B = blockIdx.z ? B1 : B0;
    float* C = blockIdx.z ? C1 : C0;
    const int bm = blockIdx.y * 128;
    const int bn = blockIdx.x * 128;
    const int tid = threadIdx.x, warp = tid >> 5, lane = tid & 31;
    const int wm = warp >> 2, wn = warp & 3;   // warp tile 64(m) x 32(n)

    float c[4][4][4];
#pragma unroll
    for (int i = 0; i < 4; i++)
#pragma unroll
        for (int j = 0; j < 4; j++)
#pragma unroll
            for (int r = 0; r < 4; r++) c[i][j][r] = 0.f;

    const int T = K / 32;

    auto issue_stage = [&](int t) {
        const uint32_t stg = sb + (t % GEMM_STAGES) * STAGE_F * 4;
        const int k0 = t * 32;
#pragma unroll
        for (int i = 0; i < 4; i++) {
            const int v = tid + i * 256;
            const int row = v >> 3, kq4 = v & 7;
            const int kt = kq4 >> 1;
            const int rg = ((kq4 & 1) << 1) | ((row & 8) >> 3);
            const int mtg = (row >> 4) & 7;
            const int lnb = (((row & 7) << 2) ^ (kt << 3)) ^ (rg << 2);
            const int offA = ((kt * 8 + mtg) * 4 + rg) * 32 + lnb;
            const float* src = &A[(size_t)(bm + row) * K + k0 + kq4 * 4];
            CP_ASYNC16(stg + offA * 4, src, (bm + row < M) ? 16 : 0);
        }
#pragma unroll
        for (int i = 0; i < 4; i++) {
            const int v = tid + i * 256;
            const int kq = v >> 5, n4 = (v & 31) * 4;
            const int offB = 4096 + kq * 128 + (n4 ^ ((kq & 3) << 3));
            const float* src = &B[(size_t)(k0 + kq) * N + bn + n4];
            CP_ASYNC16(stg + offB * 4, src, 16);
        }
        CP_COMMIT();
    };

    issue_stage(0);
    if (T > 1) issue_stage(1);

    const int xorn = (lane & 3) << 3;
    const int g = lane >> 2, tq = lane & 3;

    for (int t = 0; t < T; t++) {
        if (t + 1 < T) asm volatile("cp.async.wait_group 1;" ::: "memory");
        else           asm volatile("cp.async.wait_group 0;" ::: "memory");
        __syncthreads();
        const float* s = smem + (t % GEMM_STAGES) * STAGE_F;
#pragma unroll
        for (int kt = 0; kt < 4; kt++) {
            uint32_t bh[4][2], bl[4][2];
#pragma unroll
            for (int nt = 0; nt < 4; nt++) {
                const int nl = wn * 32 + nt * 8 + g;
#pragma unroll
                for (int r = 0; r < 2; r++) {
                    const int k = kt * 8 + tq + r * 4;
                    const float v = s[4096 + k * 128 + (nl ^ xorn)];
                    const float h = tf32f(v);
                    bh[nt][r] = __float_as_uint(h);
                    bl[nt][r] = __float_as_uint(v - h);
                }
            }
#pragma unroll
            for (int mt = 0; mt < 4; mt++) {
                const int mtg = wm * 4 + mt;
                uint32_t ah[4], al[4];
#pragma unroll
                for (int r = 0; r < 4; r++) {
                    const int lnp = (lane ^ (kt * 8)) ^ (r * 4);
                    const float v = s[((kt * 8 + mtg) * 4 + r) * 32 + lnp];
                    const float h = tf32f(v);
                    ah[r] = __float_as_uint(h);
                    al[r] = __float_as_uint(v - h);
                }
#pragma unroll
                for (int nt = 0; nt < 4; nt++) {
                    mma_tf32(c[mt][nt], ah, bh[nt]);
                    mma_tf32(c[mt][nt], ah, bl[nt]);
                    mma_tf32(c[mt][nt], al, bh[nt]);
                }
            }
        }
        if (t + 2 < T) issue_stage(t + 2);
    }

#pragma unroll
    for (int mt = 0; mt < 4; mt++) {
        const int r0 = bm + wm * 64 + mt * 16 + g;
#pragma unroll
        for (int nt = 0; nt < 4; nt++) {
            const int col = bn + wn * 32 + nt * 8 + tq * 2;
            if (r0 < M)
                *reinterpret_cast<float2*>(&C[(size_t)r0 * N + col]) =
                    make_float2(c[mt][nt][0], c[mt][nt][1]);
            if (r0 + 8 < M)
                *reinterpret_cast<float2*>(&C[(size_t)(r0 + 8) * N + col]) =
                    make_float2(c[mt][nt][2], c[mt][nt][3]);
        }
    }
}

// ---------------- CSR build ----------------
__global__ void zero_int_kernel(int* p, int n) {
    int i = blockIdx.x * blockDim.x + threadIdx.x;
    if (i < n) p[i] = 0;
}
__global__ void degree_kernel(const int* __restrict__ dst, int* __restrict__ deg, int E) {
    int i = blockIdx.x * blockDim.x + threadIdx.x;
    if (i < E) atomicAdd(&deg[dst[i]], 1);
}
__global__ void scan_kernel(const int* __restrict__ deg, int* __restrict__ ptr,
                            int* __restrict__ work, int n) {
    __shared__ int sm[1024];
    const int tid = threadIdx.x;
    const int chunk = (n + 1023) >> 10;
    const int start = tid * chunk;
    const int end = min(start + chunk, n);
    int s = 0;
    for (int i = start; i < end; i++) s += deg[i];
    sm[tid] = s;
    __syncthreads();
    for (int off = 1; off < 1024; off <<= 1) {
        int v = (tid >= off) ? sm[tid - off] : 0;
        __syncthreads();
        sm[tid] += v;
        __syncthreads();
    }
    int excl = (tid == 0) ? 0 : sm[tid - 1];
    for (int i = start; i < end; i++) {
        ptr[i] = excl;
        work[i] = excl;
        excl += deg[i];
    }
    if (tid == 0) ptr[n] = sm[1023];
}
__global__ void scatter_kernel(const int* __restrict__ src, const int* __restrict__ dst,
                               int* __restrict__ work, int* __restrict__ eid,
                               int* __restrict__ esrc, int E) {
    int e = blockIdx.x * blockDim.x + threadIdx.x;
    if (e < E) {
        int p = atomicAdd(&work[dst[e]], 1);
        eid[p] = e;
        esrc[p] = src[e];
    }
}

// ---------------- fused single-pass attention, head-split + edge prefetch ----------
// HW = heads per warp; blockIdx.y = head group. Online softmax in registers; the
// edge loop prefetches next edge's src row + edge attrs while computing current.
template <int H, int C, int HW, bool EA, bool RELU>
__global__ void __launch_bounds__(256, 2)
node_attn_kernel(const float* __restrict__ xl, const float* __restrict__ xr,
                 const float* __restrict__ ea, const float* __restrict__ We,
                 const float* __restrict__ att, const float* __restrict__ bias,
                 const int* __restrict__ ptr, const int* __restrict__ eid,
                 const int* __restrict__ esrc,
                 float* __restrict__ out, int n) {
    constexpr int HC = H * C;
    constexpr int WC = HW * C;          // channels owned by this warp's head group
    constexpr int F4 = WC / 128;        // float4 slots per lane
    __shared__ float s_att[WC];
    __shared__ float s_We[EA ? 8 * WC : 4];
    const int cb = blockIdx.y * WC;     // channel base of this head group
    for (int i = threadIdx.x; i < WC; i += blockDim.x) s_att[i] = att[cb + i];
    if (EA)
        for (int i = threadIdx.x; i < 8 * WC; i += blockDim.x) {
            const int k = i / WC, c = i - k * WC;
            s_We[i] = We[k * HC + cb + c];
        }
    __syncthreads();

    const int warp = threadIdx.x >> 5, lane = threadIdx.x & 31;
    const int d = blockIdx.x * 8 + warp;
    if (d >= n) return;
    const int p0 = ptr[d], p1 = ptr[d + 1];

    int lidx[F4];
#pragma unroll
    for (int j = 0; j < F4; j++) lidx[j] = lane * 4 + j * 128;   // local channel idx

    float4 xrv[F4];
#pragma unroll
    for (int j = 0; j < F4; j++)
        xrv[j] = *reinterpret_cast<const float4*>(xr + (size_t)d * HC + cb + lidx[j]);

    float mxj[F4], denj[F4];
    float4 acc[F4];
#pragma unroll
    for (int j = 0; j < F4; j++) {
        mxj[j] = -CUDART_INF_F;
        denj[j] = 0.f;
        acc[j] = make_float4(0.f, 0.f, 0.f, 0.f);
    }

    // ---- prefetch edge p0 ----
    float4 avN[F4];
    float earN[8];
    if (p0 < p1) {
        const int s = esrc[p0];
        const float* xs = xl + (size_t)s * HC + cb;
#pragma unroll
        for (int j = 0; j < F4; j++)
            avN[j] = *reinterpret_cast<const float4*>(xs + lidx[j]);
        if (EA) {
            const float* er = ea + (size_t)eid[p0] * 8;
#pragma unroll
            for (int k = 0; k < 8; k++) earN[k] = __ldg(er + k);
        }
    }

    for (int p = p0; p < p1; p++) {
        float4 av[F4];
        float earC[8];
#pragma unroll
        for (int j = 0; j < F4; j++) av[j] = avN[j];
        if (EA) {
#pragma unroll
            for (int k = 0; k < 8; k++) earC[k] = earN[k];
        }
        // ---- issue next edge's loads before computing current ----
        if (p + 1 < p1) {
            const int s = esrc[p + 1];
            const float* xs = xl + (size_t)s * HC + cb;
#pragma unroll
            for (int j = 0; j < F4; j++)
                avN[j] = *reinterpret_cast<const float4*>(xs + lidx[j]);
            if (EA) {
                const float* er = ea + (size_t)eid[p + 1] * 8;
#pragma unroll
                for (int k = 0; k < 8; k++) earN[k] = __ldg(er + k);
            }
        }
        // ---- current edge: dot + leaky relu + att ----
        float dotj[F4];
#pragma unroll
        for (int j = 0; j < F4; j++) {
            float vx = av[j].x + xrv[j].x, vy = av[j].y + xrv[j].y;
            float vz = av[j].z + xrv[j].z, vw = av[j].w + xrv[j].w;
            if (EA) {
#pragma unroll
                for (int k = 0; k < 8; k++) {
                    float4 w = *reinterpret_cast<const float4*>(&s_We[k * WC + lidx[j]]);
                    vx += earC[k] * w.x; vy += earC[k] * w.y;
                    vz += earC[k] * w.z; vw += earC[k] * w.w;
                }
            }
            vx = (vx >= 0.f) ? vx : 0.2f * vx;
            vy = (vy >= 0.f) ? vy : 0.2f * vy;
            vz = (vz >= 0.f) ? vz : 0.2f * vz;
            vw = (vw >= 0.f) ? vw : 0.2f * vw;
            float4 t = *reinterpret_cast<const float4*>(&s_att[lidx[j]]);
            dotj[j] = t.x * vx + t.y * vy + t.z * vz + t.w * vw;
        }
        float tj[F4];
        if constexpr (C >= 128) {
            constexpr int JPH = C / 128;
#pragma unroll
            for (int h = 0; h < HW; h++) {
                float sacc = 0.f;
#pragma unroll
                for (int m = 0; m < JPH; m++) sacc += dotj[h * JPH + m];
#pragma unroll
                for (int o = 16; o > 0; o >>= 1) sacc += __shfl_xor_sync(0xffffffffu, sacc, o);
#pragma unroll
                for (int m = 0; m < JPH; m++) tj[h * JPH + m] = sacc;
            }
        } else {   // C == 64: head spans 16 lanes
#pragma unroll
            for (int j = 0; j < F4; j++) {
                float sacc = dotj[j];
#pragma unroll
                for (int o = 8; o > 0; o >>= 1) sacc += __shfl_xor_sync(0xffffffffu, sacc, o);
                tj[j] = sacc;
            }
        }
#pragma unroll
        for (int j = 0; j < F4; j++) {
            const float mn = fmaxf(mxj[j], tj[j]);
            const float so = __expf(mxj[j] - mn);
            const float e  = __expf(tj[j] - mn);
            mxj[j] = mn;
            denj[j] = denj[j] * so + e;
            acc[j].x = acc[j].x * so + e * av[j].x;
            acc[j].y = acc[j].y * so + e * av[j].y;
            acc[j].z = acc[j].z * so + e * av[j].z;
            acc[j].w = acc[j].w * so + e * av[j].w;
        }
    }

#pragma unroll
    for (int j = 0; j < F4; j++) {
        const float inv = 1.f / (denj[j] + 1e-16f);
        float4 b = *reinterpret_cast<const float4*>(bias + cb + lidx[j]);
        float4 o = make_float4(acc[j].x * inv + b.x, acc[j].y * inv + b.y,
                               acc[j].z * inv + b.z, acc[j].w * inv + b.w);
        if (RELU) {
            o.x = fmaxf(o.x, 0.f); o.y = fmaxf(o.y, 0.f);
            o.z = fmaxf(o.z, 0.f); o.w = fmaxf(o.w, 0.f);
        }
        *reinterpret_cast<float4*>(out + (size_t)d * HC + cb + lidx[j]) = o;
    }
}

// ---------------- readout ----------------
__global__ void last_idx_kernel(const int* __restrict__ n_nodes, int* __restrict__ last, int G) {
    if (threadIdx.x == 0 && blockIdx.x == 0) {
        int s = 0;
        for (int i = 0; i < G; i++) { s += n_nodes[i]; last[i] = s - 1; }
    }
}
__global__ void fc_kernel(const float* __restrict__ h, const int* __restrict__ last,
                          const float* __restrict__ W1, const float* __restrict__ b1,
                          const float* __restrict__ W2, const float* __restrict__ b2,
                          float* __restrict__ out) {
    __shared__ float row[384];
    __shared__ float red[64];
    const int g = blockIdx.x, t = threadIdx.x;
    const int node = last[g];
    for (int i = t; i < 384; i += 64) row[i] = h[(size_t)node * 384 + i];
    __syncthreads();
    float acc = b1[t];
    for (int k = 0; k < 384; k++) acc += row[k] * W1[k * 64 + t];
    acc = fmaxf(acc, 0.f);
    red[t] = acc * W2[t];
    __syncthreads();
    if (t < 32) {
        float p = red[t] + red[t + 32];
#pragma unroll
        for (int o = 16; o > 0; o >>= 1) p += __shfl_xor_sync(0xffffffffu, p, o);
        if (t == 0) out[g] = p + b2[0];
    }
}

// ---------------- launch ----------------
extern "C" void kernel_launch(void* const* d_in, const int* in_sizes, int n_in,
                              void* d_out, int out_size) {
    const float* x       = (const float*)d_in[0];
    const float* ea      = (const float*)d_in[1];
    const float* Wl1     = (const float*)d_in[2];
    const float* Wr1     = (const float*)d_in[3];
    const float* We1     = (const float*)d_in[4];
    const float* att1    = (const float*)d_in[5];
    const float* b1      = (const float*)d_in[6];
    const float* Wl2     = (const float*)d_in[7];
    const float* Wr2     = (const float*)d_in[8];
    const float* We2     = (const float*)d_in[9];
    const float* att2    = (const float*)d_in[10];
    const float* b2      = (const float*)d_in[11];
    const float* Wlp     = (const float*)d_in[12];
    const float* Wrp     = (const float*)d_in[13];
    const float* attp    = (const float*)d_in[14];
    const float* bp      = (const float*)d_in[15];
    const float* Wfc1    = (const float*)d_in[16];
    const float* bfc1    = (const float*)d_in[17];
    const float* Wfc2    = (const float*)d_in[18];
    const float* bfc2    = (const float*)d_in[19];
    const int*   ei      = (const int*)d_in[20];
    const int*   eim     = (const int*)d_in[21];
    const int*   n_nodes = (const int*)d_in[22];

    const int N = N_NODES, E = N_EDGES;
    const int* src  = ei;
    const int* dst  = ei + E;
    const int* srcm = eim;
    const int* dstm = eim + E;

    float *bufA, *bufB, *bufC, *bufD;
    int *deg, *work, *ptr, *eid, *esrc, *ptr2, *eid2, *esrc2, *last;
    cudaGetSymbolAddress((void**)&bufA, g_bufA);
    cudaGetSymbolAddress((void**)&bufB, g_bufB);
    cudaGetSymbolAddress((void**)&bufC, g_bufC);
    cudaGetSymbolAddress((void**)&bufD, g_bufD);
    cudaGetSymbolAddress((void**)&deg, g_deg);
    cudaGetSymbolAddress((void**)&work, g_work);
    cudaGetSymbolAddress((void**)&ptr, g_ptr);
    cudaGetSymbolAddress((void**)&eid, g_eid);
    cudaGetSymbolAddress((void**)&esrc, g_esrc);
    cudaGetSymbolAddress((void**)&ptr2, g_ptr2);
    cudaGetSymbolAddress((void**)&eid2, g_eid2);
    cudaGetSymbolAddress((void**)&esrc2, g_esrc2);
    cudaGetSymbolAddress((void**)&last, g_last);

    cudaFuncSetAttribute(gemm_mma_kernel, cudaFuncAttributeMaxDynamicSharedMemorySize, GEMM_SMEM);

    const int MB = (N + 127) / 128;
    const int EB = (E + 255) / 256;
    const int NB = (N + 255) / 256;

    // ===== master CSR (partial) + layer-1 GEMM early =====
    zero_int_kernel<<<NB, 256>>>(deg, N);
    degree_kernel<<<EB, 256>>>(dstm, deg, E);
    scan_kernel<<<1, 1024>>>(deg, ptr2, work, N);
    gemm_mma_kernel<<<dim3(1024 / 128, MB, 2), 256, GEMM_SMEM>>>(x, Wl1, Wr1, bufA, bufB, N, 1024, 64);
    scatter_kernel<<<EB, 256>>>(srcm, dstm, work, eid2, esrc2, E);

    // ===== main CSR =====
    zero_int_kernel<<<NB, 256>>>(deg, N);
    degree_kernel<<<EB, 256>>>(dst, deg, E);
    scan_kernel<<<1, 1024>>>(deg, ptr, work, N);
    scatter_kernel<<<EB, 256>>>(src, dst, work, eid, esrc, E);

    // ===== Layer 1 attention: 2 heads/warp, 2 head groups (R11 config) + prefetch =====
    node_attn_kernel<4, 256, 2, true, true><<<dim3((N + 7) / 8, 2), 256>>>(
        bufA, bufB, ea, We1, att1, b1, ptr, eid, esrc, bufC, N);

    // ===== Layer 2 =====
    gemm_mma_kernel<<<dim3(256 / 128, MB, 2), 256, GEMM_SMEM>>>(bufC, Wl2, Wr2, bufA, bufB, N, 256, 1024);
    node_attn_kernel<4, 64, 4, true, true><<<dim3((N + 7) / 8, 1), 256>>>(
        bufA, bufB, ea, We2, att2, b2, ptr, eid, esrc, bufD, N);

    // ===== Layer 3 (master edges) =====
    gemm_mma_kernel<<<dim3(384 / 128, MB, 2), 256, GEMM_SMEM>>>(bufD, Wlp, Wrp, bufA, bufB, N, 384, 256);
    node_attn_kernel<6, 64, 6, false, false><<<dim3((N + 7) / 8, 1), 256>>>(
        bufA, bufB, nullptr, nullptr, attp, bp, ptr2, eid2, esrc2, bufC, N);

    // ===== readout + MLP head =====
    last_idx_kernel<<<1, 32>>>(n_nodes, last, N_GRAPHS);
    fc_kernel<<<N_GRAPHS, 64>>>(bufC, last, Wfc1, bfc1, Wfc2, bfc2, (float*)d_out);
}

// round 14
// speedup vs baseline: 1.0531x; 1.0040x over previous
#include <cuda_runtime.h>
#include <cstdint>
#include <math_constants.h>

#define N_NODES  20000
#define N_EDGES  160000
#define N_GRAPHS 100

// ---------------- scratch (device globals; no allocation allowed) ----------------
__device__ float g_bufA[N_NODES * 1024];
__device__ float g_bufB[N_NODES * 1024];
__device__ float g_bufC[N_NODES * 1024];
__device__ float g_bufD[N_NODES * 1024];
__device__ int   g_deg[N_NODES];
__device__ int   g_work[N_NODES];
__device__ int   g_ptr[N_NODES + 1];
__device__ int   g_eid[N_EDGES];
__device__ int   g_esrc[N_EDGES];
__device__ int   g_ptr2[N_NODES + 1];
__device__ int   g_eid2[N_EDGES];
__device__ int   g_esrc2[N_EDGES];
__device__ int   g_last[N_GRAPHS];

// ================= tensor-core GEMM (mma.sync m16n8k8 tf32, 3-term split) ==========
__device__ __forceinline__ float tf32f(float x) {
    uint32_t u;
    asm("cvt.rna.tf32.f32 %0, %1;" : "=r"(u) : "f"(x));
    return __uint_as_float(u);
}
__device__ __forceinline__ void mma_tf32(float* d, const uint32_t* a, const uint32_t* b) {
    asm volatile("mma.sync.aligned.m16n8k8.row.col.f32.tf32.tf32.f32 "
                 "{%0,%1,%2,%3}, {%4,%5,%6,%7}, {%8,%9}, {%0,%1,%2,%3};"
                 : "+f"(d[0]), "+f"(d[1]), "+f"(d[2]), "+f"(d[3])
                 : "r"(a[0]), "r"(a[1]), "r"(a[2]), "r"(a[3]), "r"(b[0]), "r"(b[1]));
}
__device__ __forceinline__ uint32_t smem_u32(const void* p) {
    uint32_t a;
    asm("{ .reg .u64 t; cvta.to.shared.u64 t, %1; cvt.u32.u64 %0, t; }" : "=r"(a) : "l"(p));
    return a;
}
#define CP_ASYNC16(dst, src, pb) \
    asm volatile("cp.async.cg.shared.global [%0], [%1], 16, %2;" :: "r"(dst), "l"(src), "r"(pb))
#define CP_COMMIT() asm volatile("cp.async.commit_group;" ::: "memory")

#define STAGE_F 8192
#define GEMM_STAGES 3
#define GEMM_SMEM (GEMM_STAGES * STAGE_F * 4)   // 96 KB

__global__ void __launch_bounds__(256, 2)
gemm_mma_kernel(const float* __restrict__ A,
                const float* __restrict__ B0, const float* __restrict__ B1,
                float* __restrict__ C0, float* __restrict__ C1,
                int M, int N, int K) {
    extern __shared__ __align__(16) float smem[];
    const uint32_t sb = smem_u32(smem);
    const float* B = blockIdx.z ? B1 : B0;
    float* C = blockIdx.z ? C1 : C0;
    const int bm = blockIdx.y * 128;
    const int bn = blockIdx.x * 128;
    const int tid = threadIdx.x, warp = tid >> 5, lane = tid & 31;
    const int wm = warp >> 2, wn = warp & 3;   // warp tile 64(m) x 32(n)

    float c[4][4][4];
#pragma unroll
    for (int i = 0; i < 4; i++)
#pragma unroll
        for (int j = 0; j < 4; j++)
#pragma unroll
            for (int r = 0; r < 4; r++) c[i][j][r] = 0.f;

    const int T = K / 32;

    auto issue_stage = [&](int t) {
        const uint32_t stg = sb + (t % GEMM_STAGES) * STAGE_F * 4;
        const int k0 = t * 32;
#pragma unroll
        for (int i = 0; i < 4; i++) {
            const int v = tid + i * 256;
            const int row = v >> 3, kq4 = v & 7;
            const int kt = kq4 >> 1;
            const int rg = ((kq4 & 1) << 1) | ((row & 8) >> 3);
            const int mtg = (row >> 4) & 7;
            const int lnb = (((row & 7) << 2) ^ (kt << 3)) ^ (rg << 2);
            const int offA = ((kt * 8 + mtg) * 4 + rg) * 32 + lnb;
            const float* src = &A[(size_t)(bm + row) * K + k0 + kq4 * 4];
            CP_ASYNC16(stg + offA * 4, src, (bm + row < M) ? 16 : 0);
        }
#pragma unroll
        for (int i = 0; i < 4; i++) {
            const int v = tid + i * 256;
            const int kq = v >> 5, n4 = (v & 31) * 4;
            const int offB = 4096 + kq * 128 + (n4 ^ ((kq & 3) << 3));
            const float* src = &B[(size_t)(k0 + kq) * N + bn + n4];
            CP_ASYNC16(stg + offB * 4, src, 16);
        }
        CP_COMMIT();
    };

    issue_stage(0);
    if (T > 1) issue_stage(1);

    const int xorn = (lane & 3) << 3;
    const int g = lane >> 2, tq = lane & 3;

    for (int t = 0; t < T; t++) {
        if (t + 1 < T) asm volatile("cp.async.wait_group 1;" ::: "memory");
        else           asm volatile("cp.async.wait_group 0;" ::: "memory");
        __syncthreads();
        const float* s = smem + (t % GEMM_STAGES) * STAGE_F;
#pragma unroll
        for (int kt = 0; kt < 4; kt++) {
            uint32_t bh[4][2], bl[4][2];
#pragma unroll
            for (int nt = 0; nt < 4; nt++) {
                const int nl = wn * 32 + nt * 8 + g;
#pragma unroll
                for (int r = 0; r < 2; r++) {
                    const int k = kt * 8 + tq + r * 4;
                    const float v = s[4096 + k * 128 + (nl ^ xorn)];
                    const float h = tf32f(v);
                    bh[nt][r] = __float_as_uint(h);
                    bl[nt][r] = __float_as_uint(v - h);
                }
            }
#pragma unroll
            for (int mt = 0; mt < 4; mt++) {
                const int mtg = wm * 4 + mt;
                uint32_t ah[4], al[4];
#pragma unroll
                for (int r = 0; r < 4; r++) {
                    const int lnp = (lane ^ (kt * 8)) ^ (r * 4);
                    const float v = s[((kt * 8 + mtg) * 4 + r) * 32 + lnp];
                    const float h = tf32f(v);
                    ah[r] = __float_as_uint(h);
                    al[r] = __float_as_uint(v - h);
                }
                // Three nt-sweeps: dependent MMAs on the same accumulator are
                // separated by 4 independent MMAs (RAW distance 1 -> 4).
#pragma unroll
                for (int nt = 0; nt < 4; nt++) mma_tf32(c[mt][nt], ah, bh[nt]);
#pragma unroll
                for (int nt = 0; nt < 4; nt++) mma_tf32(c[mt][nt], ah, bl[nt]);
#pragma unroll
                for (int nt = 0; nt < 4; nt++) mma_tf32(c[mt][nt], al, bh[nt]);
            }
        }
        if (t + 2 < T) issue_stage(t + 2);
    }

#pragma unroll
    for (int mt = 0; mt < 4; mt++) {
        const int r0 = bm + wm * 64 + mt * 16 + g;
#pragma unroll
        for (int nt = 0; nt < 4; nt++) {
            const int col = bn + wn * 32 + nt * 8 + tq * 2;
            if (r0 < M)
                *reinterpret_cast<float2*>(&C[(size_t)r0 * N + col]) =
                    make_float2(c[mt][nt][0], c[mt][nt][1]);
            if (r0 + 8 < M)
                *reinterpret_cast<float2*>(&C[(size_t)(r0 + 8) * N + col]) =
                    make_float2(c[mt][nt][2], c[mt][nt][3]);
        }
    }
}

// ---------------- CSR build ----------------
__global__ void zero_int_kernel(int* p, int n) {
    int i = blockIdx.x * blockDim.x + threadIdx.x;
    if (i < n) p[i] = 0;
}
__global__ void degree_kernel(const int* __restrict__ dst, int* __restrict__ deg, int E) {
    int i = blockIdx.x * blockDim.x + threadIdx.x;
    if (i < E) atomicAdd(&deg[dst[i]], 1);
}
__global__ void scan_kernel(const int* __restrict__ deg, int* __restrict__ ptr,
                            int* __restrict__ work, int n) {
    __shared__ int sm[1024];
    const int tid = threadIdx.x;
    const int chunk = (n + 1023) >> 10;
    const int start = tid * chunk;
    const int end = min(start + chunk, n);
    int s = 0;
    for (int i = start; i < end; i++) s += deg[i];
    sm[tid] = s;
    __syncthreads();
    for (int off = 1; off < 1024; off <<= 1) {
        int v = (tid >= off) ? sm[tid - off] : 0;
        __syncthreads();
        sm[tid] += v;
        __syncthreads();
    }
    int excl = (tid == 0) ? 0 : sm[tid - 1];
    for (int i = start; i < end; i++) {
        ptr[i] = excl;
        work[i] = excl;
        excl += deg[i];
    }
    if (tid == 0) ptr[n] = sm[1023];
}
__global__ void scatter_kernel(const int* __restrict__ src, const int* __restrict__ dst,
                               int* __restrict__ work, int* __restrict__ eid,
                               int* __restrict__ esrc, int E) {
    int e = blockIdx.x * blockDim.x + threadIdx.x;
    if (e < E) {
        int p = atomicAdd(&work[dst[e]], 1);
        eid[p] = e;
        esrc[p] = src[e];
    }
}

// ---------------- fused single-pass attention, head-split + edge prefetch ----------
template <int H, int C, int HW, bool EA, bool RELU>
__global__ void __launch_bounds__(256, 2)
node_attn_kernel(const float* __restrict__ xl, const float* __restrict__ xr,
                 const float* __restrict__ ea, const float* __restrict__ We,
                 const float* __restrict__ att, const float* __restrict__ bias,
                 const int* __restrict__ ptr, const int* __restrict__ eid,
                 const int* __restrict__ esrc,
                 float* __restrict__ out, int n) {
    constexpr int HC = H * C;
    constexpr int WC = HW * C;          // channels owned by this warp's head group
    constexpr int F4 = WC / 128;        // float4 slots per lane
    __shared__ float s_att[WC];
    __shared__ float s_We[EA ? 8 * WC : 4];
    const int cb = blockIdx.y * WC;     // channel base of this head group
    for (int i = threadIdx.x; i < WC; i += blockDim.x) s_att[i] = att[cb + i];
    if (EA)
        for (int i = threadIdx.x; i < 8 * WC; i += blockDim.x) {
            const int k = i / WC, c = i - k * WC;
            s_We[i] = We[k * HC + cb + c];
        }
    __syncthreads();

    const int warp = threadIdx.x >> 5, lane = threadIdx.x & 31;
    const int d = blockIdx.x * 8 + warp;
    if (d >= n) return;
    const int p0 = ptr[d], p1 = ptr[d + 1];

    int lidx[F4];
#pragma unroll
    for (int j = 0; j < F4; j++) lidx[j] = lane * 4 + j * 128;   // local channel idx

    float4 xrv[F4];
#pragma unroll
    for (int j = 0; j < F4; j++)
        xrv[j] = *reinterpret_cast<const float4*>(xr + (size_t)d * HC + cb + lidx[j]);

    float mxj[F4], denj[F4];
    float4 acc[F4];
#pragma unroll
    for (int j = 0; j < F4; j++) {
        mxj[j] = -CUDART_INF_F;
        denj[j] = 0.f;
        acc[j] = make_float4(0.f, 0.f, 0.f, 0.f);
    }

    // ---- prefetch edge p0 ----
    float4 avN[F4];
    float earN[8];
    if (p0 < p1) {
        const int s = esrc[p0];
        const float* xs = xl + (size_t)s * HC + cb;
#pragma unroll
        for (int j = 0; j < F4; j++)
            avN[j] = *reinterpret_cast<const float4*>(xs + lidx[j]);
        if (EA) {
            const float* er = ea + (size_t)eid[p0] * 8;
#pragma unroll
            for (int k = 0; k < 8; k++) earN[k] = __ldg(er + k);
        }
    }

    for (int p = p0; p < p1; p++) {
        float4 av[F4];
        float earC[8];
#pragma unroll
        for (int j = 0; j < F4; j++) av[j] = avN[j];
        if (EA) {
#pragma unroll
            for (int k = 0; k < 8; k++) earC[k] = earN[k];
        }
        if (p + 1 < p1) {
            const int s = esrc[p + 1];
            const float* xs = xl + (size_t)s * HC + cb;
#pragma unroll
            for (int j = 0; j < F4; j++)
                avN[j] = *reinterpret_cast<const float4*>(xs + lidx[j]);
            if (EA) {
                const float* er = ea + (size_t)eid[p + 1] * 8;
#pragma unroll
                for (int k = 0; k < 8; k++) earN[k] = __ldg(er + k);
            }
        }
        float dotj[F4];
#pragma unroll
        for (int j = 0; j < F4; j++) {
            float vx = av[j].x + xrv[j].x, vy = av[j].y + xrv[j].y;
            float vz = av[j].z + xrv[j].z, vw = av[j].w + xrv[j].w;
            if (EA) {
#pragma unroll
                for (int k = 0; k < 8; k++) {
                    float4 w = *reinterpret_cast<const float4*>(&s_We[k * WC + lidx[j]]);
                    vx += earC[k] * w.x; vy += earC[k] * w.y;
                    vz += earC[k] * w.z; vw += earC[k] * w.w;
                }
            }
            vx = (vx >= 0.f) ? vx : 0.2f * vx;
            vy = (vy >= 0.f) ? vy : 0.2f * vy;
            vz = (vz >= 0.f) ? vz : 0.2f * vz;
            vw = (vw >= 0.f) ? vw : 0.2f * vw;
            float4 t = *reinterpret_cast<const float4*>(&s_att[lidx[j]]);
            dotj[j] = t.x * vx + t.y * vy + t.z * vz + t.w * vw;
        }
        float tj[F4];
        if constexpr (C >= 128) {
            constexpr int JPH = C / 128;
#pragma unroll
            for (int h = 0; h < HW; h++) {
                float sacc = 0.f;
#pragma unroll
                for (int m = 0; m < JPH; m++) sacc += dotj[h * JPH + m];
#pragma unroll
                for (int o = 16; o > 0; o >>= 1) sacc += __shfl_xor_sync(0xffffffffu, sacc, o);
#pragma unroll
                for (int m = 0; m < JPH; m++) tj[h * JPH + m] = sacc;
            }
        } else {   // C == 64: head spans 16 lanes
#pragma unroll
            for (int j = 0; j < F4; j++) {
                float sacc = dotj[j];
#pragma unroll
                for (int o = 8; o > 0; o >>= 1) sacc += __shfl_xor_sync(0xffffffffu, sacc, o);
                tj[j] = sacc;
            }
        }
#pragma unroll
        for (int j = 0; j < F4; j++) {
            const float mn = fmaxf(mxj[j], tj[j]);
            const float so = __expf(mxj[j] - mn);
            const float e  = __expf(tj[j] - mn);
            mxj[j] = mn;
            denj[j] = denj[j] * so + e;
            acc[j].x = acc[j].x * so + e * av[j].x;
            acc[j].y = acc[j].y * so + e * av[j].y;
            acc[j].z = acc[j].z * so + e * av[j].z;
            acc[j].w = acc[j].w * so + e * av[j].w;
        }
    }

#pragma unroll
    for (int j = 0; j < F4; j++) {
        const float inv = 1.f / (denj[j] + 1e-16f);
        float4 b = *reinterpret_cast<const float4*>(bias + cb + lidx[j]);
        float4 o = make_float4(acc[j].x * inv + b.x, acc[j].y * inv + b.y,
                               acc[j].z * inv + b.z, acc[j].w * inv + b.w);
        if (RELU) {
            o.x = fmaxf(o.x, 0.f); o.y = fmaxf(o.y, 0.f);
            o.z = fmaxf(o.z, 0.f); o.w = fmaxf(o.w, 0.f);
        }
        *reinterpret_cast<float4*>(out + (size_t)d * HC + cb + lidx[j]) = o;
    }
}

// ---------------- readout ----------------
__global__ void last_idx_kernel(const int* __restrict__ n_nodes, int* __restrict__ last, int G) {
    if (threadIdx.x == 0 && blockIdx.x == 0) {
        int s = 0;
        for (int i = 0; i < G; i++) { s += n_nodes[i]; last[i] = s - 1; }
    }
}
__global__ void fc_kernel(const float* __restrict__ h, const int* __restrict__ last,
                          const float* __restrict__ W1, const float* __restrict__ b1,
                          const float* __restrict__ W2, const float* __restrict__ b2,
                          float* __restrict__ out) {
    __shared__ float row[384];
    __shared__ float red[64];
    const int g = blockIdx.x, t = threadIdx.x;
    const int node = last[g];
    for (int i = t; i < 384; i += 64) row[i] = h[(size_t)node * 384 + i];
    __syncthreads();
    float acc = b1[t];
    for (int k = 0; k < 384; k++) acc += row[k] * W1[k * 64 + t];
    acc = fmaxf(acc, 0.f);
    red[t] = acc * W2[t];
    __syncthreads();
    if (t < 32) {
        float p = red[t] + red[t + 32];
#pragma unroll
        for (int o = 16; o > 0; o >>= 1) p += __shfl_xor_sync(0xffffffffu, p, o);
        if (t == 0) out[g] = p + b2[0];
    }
}

// ---------------- launch ----------------
extern "C" void kernel_launch(void* const* d_in, const int* in_sizes, int n_in,
                              void* d_out, int out_size) {
    const float* x       = (const float*)d_in[0];
    const float* ea      = (const float*)d_in[1];
    const float* Wl1     = (const float*)d_in[2];
    const float* Wr1     = (const float*)d_in[3];
    const float* We1     = (const float*)d_in[4];
    const float* att1    = (const float*)d_in[5];
    const float* b1      = (const float*)d_in[6];
    const float* Wl2     = (const float*)d_in[7];
    const float* Wr2     = (const float*)d_in[8];
    const float* We2     = (const float*)d_in[9];
    const float* att2    = (const float*)d_in[10];
    const float* b2      = (const float*)d_in[11];
    const float* Wlp     = (const float*)d_in[12];
    const float* Wrp     = (const float*)d_in[13];
    const float* attp    = (const float*)d_in[14];
    const float* bp      = (const float*)d_in[15];
    const float* Wfc1    = (const float*)d_in[16];
    const float* bfc1    = (const float*)d_in[17];
    const float* Wfc2    = (const float*)d_in[18];
    const float* bfc2    = (const float*)d_in[19];
    const int*   ei      = (const int*)d_in[20];
    const int*   eim     = (const int*)d_in[21];
    const int*   n_nodes = (const int*)d_in[22];

    const int N = N_NODES, E = N_EDGES;
    const int* src  = ei;
    const int* dst  = ei + E;
    const int* srcm = eim;
    const int* dstm = eim + E;

    float *bufA, *bufB, *bufC, *bufD;
    int *deg, *work, *ptr, *eid, *esrc, *ptr2, *eid2, *esrc2, *last;
    cudaGetSymbolAddress((void**)&bufA, g_bufA);
    cudaGetSymbolAddress((void**)&bufB, g_bufB);
    cudaGetSymbolAddress((void**)&bufC, g_bufC);
    cudaGetSymbolAddress((void**)&bufD, g_bufD);
    cudaGetSymbolAddress((void**)&deg, g_deg);
    cudaGetSymbolAddress((void**)&work, g_work);
    cudaGetSymbolAddress((void**)&ptr, g_ptr);
    cudaGetSymbolAddress((void**)&eid, g_eid);
    cudaGetSymbolAddress((void**)&esrc, g_esrc);
    cudaGetSymbolAddress((void**)&ptr2, g_ptr2);
    cudaGetSymbolAddress((void**)&eid2, g_eid2);
    cudaGetSymbolAddress((void**)&esrc2, g_esrc2);
    cudaGetSymbolAddress((void**)&last, g_last);

    cudaFuncSetAttribute(gemm_mma_kernel, cudaFuncAttributeMaxDynamicSharedMemorySize, GEMM_SMEM);

    const int MB = (N + 127) / 128;
    const int EB = (E + 255) / 256;
    const int NB = (N + 255) / 256;

    // ===== master CSR (partial) + layer-1 GEMM early =====
    zero_int_kernel<<<NB, 256>>>(deg, N);
    degree_kernel<<<EB, 256>>>(dstm, deg, E);
    scan_kernel<<<1, 1024>>>(deg, ptr2, work, N);
    gemm_mma_kernel<<<dim3(1024 / 128, MB, 2), 256, GEMM_SMEM>>>(x, Wl1, Wr1, bufA, bufB, N, 1024, 64);
    scatter_kernel<<<EB, 256>>>(srcm, dstm, work, eid2, esrc2, E);

    // ===== main CSR =====
    zero_int_kernel<<<NB, 256>>>(deg, N);
    degree_kernel<<<EB, 256>>>(dst, deg, E);
    scan_kernel<<<1, 1024>>>(deg, ptr, work, N);
    scatter_kernel<<<EB, 256>>>(src, dst, work, eid, esrc, E);

    // ===== Layer 1 attention: 2 heads/warp, 2 head groups + prefetch =====
    node_attn_kernel<4, 256, 2, true, true><<<dim3((N + 7) / 8, 2), 256>>>(
        bufA, bufB, ea, We1, att1, b1, ptr, eid, esrc, bufC, N);

    // ===== Layer 2 =====
    gemm_mma_kernel<<<dim3(256 / 128, MB, 2), 256, GEMM_SMEM>>>(bufC, Wl2, Wr2, bufA, bufB, N, 256, 1024);
    node_attn_kernel<4, 64, 4, true, true><<<dim3((N + 7) / 8, 1), 256>>>(
        bufA, bufB, ea, We2, att2, b2, ptr, eid, esrc, bufD, N);

    // ===== Layer 3 (master edges) =====
    gemm_mma_kernel<<<dim3(384 / 128, MB, 2), 256, GEMM_SMEM>>>(bufD, Wlp, Wrp, bufA, bufB, N, 384, 256);
    node_attn_kernel<6, 64, 6, false, false><<<dim3((N + 7) / 8, 1), 256>>>(
        bufA, bufB, nullptr, nullptr, attp, bp, ptr2, eid2, esrc2, bufC, N);

    // ===== readout + MLP head =====
    last_idx_kernel<<<1, 32>>>(n_nodes, last, N_GRAPHS);
    fc_kernel<<<N_GRAPHS, 64>>>(bufC, last, Wfc1, bfc1, Wfc2, bfc2, (float*)d_out);
}

// round 15
// speedup vs baseline: 1.4370x; 1.3645x over previous
#include <cuda_runtime.h>
#include <cstdint>
#include <math_constants.h>

#define N_NODES  20000
#define N_EDGES  160000
#define N_GRAPHS 100
#define RB_BLOCKS 157                       // ceil(20000/128)
#define ASZ (157 * 64 * 1024)               // max A-frag u32 per half (K=1024)

// ---------------- scratch (device globals; no allocation allowed) ----------------
__device__ float    g_bufA[N_NODES * 1024];
__device__ float    g_bufB[N_NODES * 1024];
__device__ float    g_bufC[N_NODES * 1024];
__device__ float    g_bufD[N_NODES * 1024];
__device__ uint32_t g_afrag[2 * ASZ];       // A fragments: hi | lo
__device__ uint32_t g_wfrag[851968];        // W fragments for all 6 weight matrices
__device__ int      g_deg[N_NODES];
__device__ int      g_work[N_NODES];
__device__ int      g_ptr[N_NODES + 1];
__device__ int      g_eid[N_EDGES];
__device__ int      g_esrc[N_EDGES];
__device__ int      g_ptr2[N_NODES + 1];
__device__ int      g_eid2[N_EDGES];
__device__ int      g_esrc2[N_EDGES];
__device__ int      g_last[N_GRAPHS];

// ================= helpers =================
__device__ __forceinline__ uint32_t smem_u32(const void* p) {
    uint32_t a;
    asm("{ .reg .u64 t; cvta.to.shared.u64 t, %1; cvt.u32.u64 %0, t; }" : "=r"(a) : "l"(p));
    return a;
}
#define CP_ASYNC16(dst, src) \
    asm volatile("cp.async.cg.shared.global [%0], [%1], 16;" :: "r"(dst), "l"(src))
#define CP_COMMIT() asm volatile("cp.async.commit_group;" ::: "memory")

// pack two fp32 into bf16x2 (lo = a0/even-k, hi = a1/odd-k), plus residual pack
__device__ __forceinline__ void bf16_split(float a0, float a1, uint32_t& h, uint32_t& l) {
    asm("cvt.rn.bf16x2.f32 %0, %1, %2;" : "=r"(h) : "f"(a1), "f"(a0));
    float h0 = __uint_as_float(h << 16);
    float h1 = __uint_as_float(h & 0xffff0000u);
    float l0 = a0 - h0, l1 = a1 - h1;
    asm("cvt.rn.bf16x2.f32 %0, %1, %2;" : "=r"(l) : "f"(l1), "f"(l0));
}

__device__ __forceinline__ void mma_bf16(float* d, uint4 a, uint2 b) {
    asm volatile("mma.sync.aligned.m16n8k16.row.col.f32.bf16.bf16.f32 "
                 "{%0,%1,%2,%3}, {%4,%5,%6,%7}, {%8,%9}, {%0,%1,%2,%3};"
                 : "+f"(d[0]), "+f"(d[1]), "+f"(d[2]), "+f"(d[3])
                 : "r"(a.x), "r"(a.y), "r"(a.z), "r"(a.w), "r"(b.x), "r"(b.y));
}

// ================= fragment pre-conversion =================
// A frag layout (u32): [rb][ktg][mt(8)][lane(32)*4 + rg(4)]
// row = rb*128 + mt*16 + (rg&1)*8 + (lane>>2); k = ktg*16 + ((rg>>1)&1)*8 + (lane&3)*2
__global__ void convA_kernel(const float* __restrict__ A, uint32_t* __restrict__ hi,
                             uint32_t* __restrict__ lo, int M, int K, int KT) {
    const int o = blockIdx.x * 256 + threadIdx.x;
    const int rg = o & 3, lane = (o >> 2) & 31, mt = (o >> 7) & 7;
    const int ktg = (o >> 10) % KT, rb = o / (KT << 10);
    const int row = rb * 128 + mt * 16 + (rg & 1) * 8 + (lane >> 2);
    const int k = ktg * 16 + ((rg >> 1) & 1) * 8 + (lane & 3) * 2;
    float a0 = 0.f, a1 = 0.f;
    if (row < M) {
        const float* p = A + (size_t)row * K + k;
        a0 = p[0]; a1 = p[1];
    }
    uint32_t h, l;
    bf16_split(a0, a1, h, l);
    hi[o] = h; lo[o] = l;
}

// W frag layout (u32): [nb][ktg][nt(16)][lane(32)*2 + rg(2)]
// n = nb*128 + nt*8 + (lane>>2); k = ktg*16 + rg*8 + (lane&3)*2
__global__ void convW_kernel(const float* __restrict__ W, uint32_t* __restrict__ hi,
                             uint32_t* __restrict__ lo, int N, int K) {
    const int KT = K >> 4;
    const int o = blockIdx.x * 256 + threadIdx.x;
    const int rg = o & 1, lane = (o >> 1) & 31, nt = (o >> 6) & 15;
    const int ktg = (o >> 10) % KT, nb = o / (KT << 10);
    const int n = nb * 128 + nt * 8 + (lane >> 2);
    const int k = ktg * 16 + rg * 8 + (lane & 3) * 2;
    const float a0 = W[(size_t)k * N + n];
    const float a1 = W[(size_t)(k + 1) * N + n];
    uint32_t h, l;
    bf16_split(a0, a1, h, l);
    hi[o] = h; lo[o] = l;
}

// ================= bf16x3 fragment GEMM =================
// stage (u32): A_hi[0,2048) A_lo[2048,4096) B_hi[4096,6144) B_lo[6144,8192) = 32KB
#define STG_U32 8192
#define GEMM_SMEM (3 * STG_U32 * 4)   // 96 KB

__global__ void __launch_bounds__(256, 2)
gemm_bf16_kernel(const uint32_t* __restrict__ Ah, const uint32_t* __restrict__ Al,
                 const uint32_t* __restrict__ Bh0, const uint32_t* __restrict__ Bl0,
                 const uint32_t* __restrict__ Bh1, const uint32_t* __restrict__ Bl1,
                 float* __restrict__ C0, float* __restrict__ C1,
                 int M, int N, int K) {
    extern __shared__ __align__(16) uint32_t smem[];
    const uint32_t sb = smem_u32(smem);
    const uint32_t* Bh = blockIdx.z ? Bh1 : Bh0;
    const uint32_t* Bl = blockIdx.z ? Bl1 : Bl0;
    float* C = blockIdx.z ? C1 : C0;
    const int KT = K >> 4, T = K >> 5;
    const int tid = threadIdx.x, warp = tid >> 5, lane = tid & 31;
    const int wm = warp >> 2, wn = warp & 3;     // warp tile 64(m) x 32(n)
    const int bm = blockIdx.y * 128, bn = blockIdx.x * 128;

    const uint32_t* sAh = Ah + (size_t)blockIdx.y * KT * 1024;
    const uint32_t* sAl = Al + (size_t)blockIdx.y * KT * 1024;
    const uint32_t* sBh = Bh + (size_t)blockIdx.x * KT * 1024;
    const uint32_t* sBl = Bl + (size_t)blockIdx.x * KT * 1024;

    float c[4][4][4];
#pragma unroll
    for (int i = 0; i < 4; i++)
#pragma unroll
        for (int j = 0; j < 4; j++)
#pragma unroll
            for (int r = 0; r < 4; r++) c[i][j][r] = 0.f;

    auto issue = [&](int t) {
        const uint32_t dst = sb + (t % 3) * STG_U32 * 4;
        const size_t off = (size_t)(2 * t) * 1024;   // two kt16 groups per stage
        const uint32_t* s0 = sAh + off;
        const uint32_t* s1 = sAl + off;
        const uint32_t* s2 = sBh + off;
        const uint32_t* s3 = sBl + off;
#pragma unroll
        for (int i = 0; i < 2; i++) {
            const int idx = (tid + i * 256) * 4;     // u32 offset of 16B chunk
            CP_ASYNC16(dst + idx * 4,                s0 + idx);
            CP_ASYNC16(dst + (2048 + idx) * 4,       s1 + idx);
            CP_ASYNC16(dst + (4096 + idx) * 4,       s2 + idx);
            CP_ASYNC16(dst + (6144 + idx) * 4,       s3 + idx);
        }
        CP_COMMIT();
    };

    issue(0);
    if (T > 1) issue(1);

    const int g = lane >> 2, tq = lane & 3;

    for (int t = 0; t < T; t++) {
        if (t + 1 < T) asm volatile("cp.async.wait_group 1;" ::: "memory");
        else           asm volatile("cp.async.wait_group 0;" ::: "memory");
        __syncthreads();
        const uint32_t* s = smem + (t % 3) * STG_U32;
#pragma unroll
        for (int kt = 0; kt < 2; kt++) {
            uint2 bh[4], bl[4];
#pragma unroll
            for (int nt = 0; nt < 4; nt++) {
                const int ntg = wn * 4 + nt;
                const uint32_t* pb = s + 4096 + (kt * 16 + ntg) * 64 + lane * 2;
                bh[nt] = *reinterpret_cast<const uint2*>(pb);
                bl[nt] = *reinterpret_cast<const uint2*>(pb + 2048);
            }
#pragma unroll
            for (int mt = 0; mt < 4; mt++) {
                const int mtg = wm * 4 + mt;
                const uint32_t* pa = s + (kt * 8 + mtg) * 128 + lane * 4;
                uint4 ah = *reinterpret_cast<const uint4*>(pa);
                uint4 al = *reinterpret_cast<const uint4*>(pa + 2048);
#pragma unroll
                for (int nt = 0; nt < 4; nt++) mma_bf16(c[mt][nt], ah, bh[nt]);
#pragma unroll
                for (int nt = 0; nt < 4; nt++) mma_bf16(c[mt][nt], ah, bl[nt]);
#pragma unroll
                for (int nt = 0; nt < 4; nt++) mma_bf16(c[mt][nt], al, bh[nt]);
            }
        }
        if (t + 2 < T) issue(t + 2);
    }

#pragma unroll
    for (int mt = 0; mt < 4; mt++) {
        const int r0 = bm + wm * 64 + mt * 16 + g;
#pragma unroll
        for (int nt = 0; nt < 4; nt++) {
            const int col = bn + wn * 32 + nt * 8 + tq * 2;
            if (r0 < M)
                *reinterpret_cast<float2*>(&C[(size_t)r0 * N + col]) =
                    make_float2(c[mt][nt][0], c[mt][nt][1]);
            if (r0 + 8 < M)
                *reinterpret_cast<float2*>(&C[(size_t)(r0 + 8) * N + col]) =
                    make_float2(c[mt][nt][2], c[mt][nt][3]);
        }
    }
}

// ---------------- CSR build ----------------
__global__ void zero_int_kernel(int* p, int n) {
    int i = blockIdx.x * blockDim.x + threadIdx.x;
    if (i < n) p[i] = 0;
}
__global__ void degree_kernel(const int* __restrict__ dst, int* __restrict__ deg, int E) {
    int i = blockIdx.x * blockDim.x + threadIdx.x;
    if (i < E) atomicAdd(&deg[dst[i]], 1);
}
__global__ void scan_kernel(const int* __restrict__ deg, int* __restrict__ ptr,
                            int* __restrict__ work, int n) {
    __shared__ int sm[1024];
    const int tid = threadIdx.x;
    const int chunk = (n + 1023) >> 10;
    const int start = tid * chunk;
    const int end = min(start + chunk, n);
    int s = 0;
    for (int i = start; i < end; i++) s += deg[i];
    sm[tid] = s;
    __syncthreads();
    for (int off = 1; off < 1024; off <<= 1) {
        int v = (tid >= off) ? sm[tid - off] : 0;
        __syncthreads();
        sm[tid] += v;
        __syncthreads();
    }
    int excl = (tid == 0) ? 0 : sm[tid - 1];
    for (int i = start; i < end; i++) {
        ptr[i] = excl;
        work[i] = excl;
        excl += deg[i];
    }
    if (tid == 0) ptr[n] = sm[1023];
}
__global__ void scatter_kernel(const int* __restrict__ src, const int* __restrict__ dst,
                               int* __restrict__ work, int* __restrict__ eid,
                               int* __restrict__ esrc, int E) {
    int e = blockIdx.x * blockDim.x + threadIdx.x;
    if (e < E) {
        int p = atomicAdd(&work[dst[e]], 1);
        eid[p] = e;
        esrc[p] = src[e];
    }
}

// ---------------- fused single-pass attention, head-split + edge prefetch ----------
template <int H, int C, int HW, bool EA, bool RELU>
__global__ void __launch_bounds__(256, 2)
node_attn_kernel(const float* __restrict__ xl, const float* __restrict__ xr,
                 const float* __restrict__ ea, const float* __restrict__ We,
                 const float* __restrict__ att, const float* __restrict__ bias,
                 const int* __restrict__ ptr, const int* __restrict__ eid,
                 const int* __restrict__ esrc,
                 float* __restrict__ out, int n) {
    constexpr int HC = H * C;
    constexpr int WC = HW * C;
    constexpr int F4 = WC / 128;
    __shared__ float s_att[WC];
    __shared__ float s_We[EA ? 8 * WC : 4];
    const int cb = blockIdx.y * WC;
    for (int i = threadIdx.x; i < WC; i += blockDim.x) s_att[i] = att[cb + i];
    if (EA)
        for (int i = threadIdx.x; i < 8 * WC; i += blockDim.x) {
            const int k = i / WC, c = i - k * WC;
            s_We[i] = We[k * HC + cb + c];
        }
    __syncthreads();

    const int warp = threadIdx.x >> 5, lane = threadIdx.x & 31;
    const int d = blockIdx.x * 8 + warp;
    if (d >= n) return;
    const int p0 = ptr[d], p1 = ptr[d + 1];

    int lidx[F4];
#pragma unroll
    for (int j = 0; j < F4; j++) lidx[j] = lane * 4 + j * 128;

    float4 xrv[F4];
#pragma unroll
    for (int j = 0; j < F4; j++)
        xrv[j] = *reinterpret_cast<const float4*>(xr + (size_t)d * HC + cb + lidx[j]);

    float mxj[F4], denj[F4];
    float4 acc[F4];
#pragma unroll
    for (int j = 0; j < F4; j++) {
        mxj[j] = -CUDART_INF_F;
        denj[j] = 0.f;
        acc[j] = make_float4(0.f, 0.f, 0.f, 0.f);
    }

    float4 avN[F4];
    float earN[8];
    if (p0 < p1) {
        const int s = esrc[p0];
        const float* xs = xl + (size_t)s * HC + cb;
#pragma unroll
        for (int j = 0; j < F4; j++)
            avN[j] = *reinterpret_cast<const float4*>(xs + lidx[j]);
        if (EA) {
            const float* er = ea + (size_t)eid[p0] * 8;
#pragma unroll
            for (int k = 0; k < 8; k++) earN[k] = __ldg(er + k);
        }
    }

    for (int p = p0; p < p1; p++) {
        float4 av[F4];
        float earC[8];
#pragma unroll
        for (int j = 0; j < F4; j++) av[j] = avN[j];
        if (EA) {
#pragma unroll
            for (int k = 0; k < 8; k++) earC[k] = earN[k];
        }
        if (p + 1 < p1) {
            const int s = esrc[p + 1];
            const float* xs = xl + (size_t)s * HC + cb;
#pragma unroll
            for (int j = 0; j < F4; j++)
                avN[j] = *reinterpret_cast<const float4*>(xs + lidx[j]);
            if (EA) {
                const float* er = ea + (size_t)eid[p + 1] * 8;
#pragma unroll
                for (int k = 0; k < 8; k++) earN[k] = __ldg(er + k);
            }
        }
        float dotj[F4];
#pragma unroll
        for (int j = 0; j < F4; j++) {
            float vx = av[j].x + xrv[j].x, vy = av[j].y + xrv[j].y;
            float vz = av[j].z + xrv[j].z, vw = av[j].w + xrv[j].w;
            if (EA) {
#pragma unroll
                for (int k = 0; k < 8; k++) {
                    float4 w = *reinterpret_cast<const float4*>(&s_We[k * WC + lidx[j]]);
                    vx += earC[k] * w.x; vy += earC[k] * w.y;
                    vz += earC[k] * w.z; vw += earC[k] * w.w;
                }
            }
            vx = (vx >= 0.f) ? vx : 0.2f * vx;
            vy = (vy >= 0.f) ? vy : 0.2f * vy;
            vz = (vz >= 0.f) ? vz : 0.2f * vz;
            vw = (vw >= 0.f) ? vw : 0.2f * vw;
            float4 t = *reinterpret_cast<const float4*>(&s_att[lidx[j]]);
            dotj[j] = t.x * vx + t.y * vy + t.z * vz + t.w * vw;
        }
        float tj[F4];
        if constexpr (C >= 128) {
            constexpr int JPH = C / 128;
#pragma unroll
            for (int h = 0; h < HW; h++) {
                float sacc = 0.f;
#pragma unroll
                for (int m = 0; m < JPH; m++) sacc += dotj[h * JPH + m];
#pragma unroll
                for (int o = 16; o > 0; o >>= 1) sacc += __shfl_xor_sync(0xffffffffu, sacc, o);
#pragma unroll
                for (int m = 0; m < JPH; m++) tj[h * JPH + m] = sacc;
            }
        } else {
#pragma unroll
            for (int j = 0; j < F4; j++) {
                float sacc = dotj[j];
#pragma unroll
                for (int o = 8; o > 0; o >>= 1) sacc += __shfl_xor_sync(0xffffffffu, sacc, o);
                tj[j] = sacc;
            }
        }
#pragma unroll
        for (int j = 0; j < F4; j++) {
            const float mn = fmaxf(mxj[j], tj[j]);
            const float so = __expf(mxj[j] - mn);
            const float e  = __expf(tj[j] - mn);
            mxj[j] = mn;
            denj[j] = denj[j] * so + e;
            acc[j].x = acc[j].x * so + e * av[j].x;
            acc[j].y = acc[j].y * so + e * av[j].y;
            acc[j].z = acc[j].z * so + e * av[j].z;
            acc[j].w = acc[j].w * so + e * av[j].w;
        }
    }

#pragma unroll
    for (int j = 0; j < F4; j++) {
        const float inv = 1.f / (denj[j] + 1e-16f);
        float4 b = *reinterpret_cast<const float4*>(bias + cb + lidx[j]);
        float4 o = make_float4(acc[j].x * inv + b.x, acc[j].y * inv + b.y,
                               acc[j].z * inv + b.z, acc[j].w * inv + b.w);
        if (RELU) {
            o.x = fmaxf(o.x, 0.f); o.y = fmaxf(o.y, 0.f);
            o.z = fmaxf(o.z, 0.f); o.w = fmaxf(o.w, 0.f);
        }
        *reinterpret_cast<float4*>(out + (size_t)d * HC + cb + lidx[j]) = o;
    }
}

// ---------------- readout ----------------
__global__ void last_idx_kernel(const int* __restrict__ n_nodes, int* __restrict__ last, int G) {
    if (threadIdx.x == 0 && blockIdx.x == 0) {
        int s = 0;
        for (int i = 0; i < G; i++) { s += n_nodes[i]; last[i] = s - 1; }
    }
}
__global__ void fc_kernel(const float* __restrict__ h, const int* __restrict__ last,
                          const float* __restrict__ W1, const float* __restrict__ b1,
                          const float* __restrict__ W2, const float* __restrict__ b2,
                          float* __restrict__ out) {
    __shared__ float row[384];
    __shared__ float red[64];
    const int g = blockIdx.x, t = threadIdx.x;
    const int node = last[g];
    for (int i = t; i < 384; i += 64) row[i] = h[(size_t)node * 384 + i];
    __syncthreads();
    float acc = b1[t];
    for (int k = 0; k < 384; k++) acc += row[k] * W1[k * 64 + t];
    acc = fmaxf(acc, 0.f);
    red[t] = acc * W2[t];
    __syncthreads();
    if (t < 32) {
        float p = red[t] + red[t + 32];
#pragma unroll
        for (int o = 16; o > 0; o >>= 1) p += __shfl_xor_sync(0xffffffffu, p, o);
        if (t == 0) out[g] = p + b2[0];
    }
}

// ---------------- launch ----------------
extern "C" void kernel_launch(void* const* d_in, const int* in_sizes, int n_in,
                              void* d_out, int out_size) {
    const float* x       = (const float*)d_in[0];
    const float* ea      = (const float*)d_in[1];
    const float* Wl1     = (const float*)d_in[2];
    const float* Wr1     = (const float*)d_in[3];
    const float* We1     = (const float*)d_in[4];
    const float* att1    = (const float*)d_in[5];
    const float* b1      = (const float*)d_in[6];
    const float* Wl2     = (const float*)d_in[7];
    const float* Wr2     = (const float*)d_in[8];
    const float* We2     = (const float*)d_in[9];
    const float* att2    = (const float*)d_in[10];
    const float* b2      = (const float*)d_in[11];
    const float* Wlp     = (const float*)d_in[12];
    const float* Wrp     = (const float*)d_in[13];
    const float* attp    = (const float*)d_in[14];
    const float* bp      = (const float*)d_in[15];
    const float* Wfc1    = (const float*)d_in[16];
    const float* bfc1    = (const float*)d_in[17];
    const float* Wfc2    = (const float*)d_in[18];
    const float* bfc2    = (const float*)d_in[19];
    const int*   ei      = (const int*)d_in[20];
    const int*   eim     = (const int*)d_in[21];
    const int*   n_nodes = (const int*)d_in[22];

    const int N = N_NODES, E = N_EDGES;
    const int* src  = ei;
    const int* dst  = ei + E;
    const int* srcm = eim;
    const int* dstm = eim + E;

    float *bufA, *bufB, *bufC, *bufD;
    uint32_t *af, *wf;
    int *deg, *work, *ptr, *eid, *esrc, *ptr2, *eid2, *esrc2, *last;
    cudaGetSymbolAddress((void**)&bufA, g_bufA);
    cudaGetSymbolAddress((void**)&bufB, g_bufB);
    cudaGetSymbolAddress((void**)&bufC, g_bufC);
    cudaGetSymbolAddress((void**)&bufD, g_bufD);
    cudaGetSymbolAddress((void**)&af, g_afrag);
    cudaGetSymbolAddress((void**)&wf, g_wfrag);
    cudaGetSymbolAddress((void**)&deg, g_deg);
    cudaGetSymbolAddress((void**)&work, g_work);
    cudaGetSymbolAddress((void**)&ptr, g_ptr);
    cudaGetSymbolAddress((void**)&eid, g_eid);
    cudaGetSymbolAddress((void**)&esrc, g_esrc);
    cudaGetSymbolAddress((void**)&ptr2, g_ptr2);
    cudaGetSymbolAddress((void**)&eid2, g_eid2);
    cudaGetSymbolAddress((void**)&esrc2, g_esrc2);
    cudaGetSymbolAddress((void**)&last, g_last);

    cudaFuncSetAttribute(gemm_bf16_kernel, cudaFuncAttributeMaxDynamicSharedMemorySize, GEMM_SMEM);

    const int EB = (E + 255) / 256;
    const int NB = (N + 255) / 256;

    // W fragment offsets (u32): per side hi then lo, sizes S = NB_w*KT*1024
    const int S1 = 8 * 4 * 1024;     // 32768
    const int S2 = 2 * 64 * 1024;    // 131072
    const int S3 = 3 * 16 * 1024;    // 49152
    uint32_t* wl1h = wf;                 uint32_t* wl1l = wl1h + S1;
    uint32_t* wr1h = wl1l + S1;          uint32_t* wr1l = wr1h + S1;
    uint32_t* wl2h = wr1l + S1;          uint32_t* wl2l = wl2h + S2;
    uint32_t* wr2h = wl2l + S2;          uint32_t* wr2l = wr2h + S2;
    uint32_t* wlph = wr2l + S2;          uint32_t* wlpl = wlph + S3;
    uint32_t* wrph = wlpl + S3;          uint32_t* wrpl = wrph + S3;

    // ===== weight fragment conversion (cheap) + CSR builds =====
    convW_kernel<<<S1 / 256, 256>>>(Wl1, wl1h, wl1l, 1024, 64);
    convW_kernel<<<S1 / 256, 256>>>(Wr1, wr1h, wr1l, 1024, 64);
    convW_kernel<<<S2 / 256, 256>>>(Wl2, wl2h, wl2l, 256, 1024);
    convW_kernel<<<S2 / 256, 256>>>(Wr2, wr2h, wr2l, 256, 1024);
    convW_kernel<<<S3 / 256, 256>>>(Wlp, wlph, wlpl, 384, 256);
    convW_kernel<<<S3 / 256, 256>>>(Wrp, wrph, wrpl, 384, 256);

    zero_int_kernel<<<NB, 256>>>(deg, N);
    degree_kernel<<<EB, 256>>>(dstm, deg, E);
    scan_kernel<<<1, 1024>>>(deg, ptr2, work, N);
    scatter_kernel<<<EB, 256>>>(srcm, dstm, work, eid2, esrc2, E);

    zero_int_kernel<<<NB, 256>>>(deg, N);
    degree_kernel<<<EB, 256>>>(dst, deg, E);
    scan_kernel<<<1, 1024>>>(deg, ptr, work, N);
    scatter_kernel<<<EB, 256>>>(src, dst, work, eid, esrc, E);

    // ===== Layer 1: conv A (K=64, KT=4) + GEMM + attention =====
    convA_kernel<<<RB_BLOCKS * 4 * 4, 256>>>(x, af, af + ASZ, N, 64, 4);
    gemm_bf16_kernel<<<dim3(8, RB_BLOCKS, 2), 256, GEMM_SMEM>>>(
        af, af + ASZ, wl1h, wl1l, wr1h, wr1l, bufA, bufB, N, 1024, 64);
    node_attn_kernel<4, 256, 2, true, true><<<dim3((N + 7) / 8, 2), 256>>>(
        bufA, bufB, ea, We1, att1, b1, ptr, eid, esrc, bufC, N);

    // ===== Layer 2: conv A (K=1024, KT=64) + GEMM + attention =====
    convA_kernel<<<RB_BLOCKS * 64 * 4, 256>>>(bufC, af, af + ASZ, N, 1024, 64);
    gemm_bf16_kernel<<<dim3(2, RB_BLOCKS, 2), 256, GEMM_SMEM>>>(
        af, af + ASZ, wl2h, wl2l, wr2h, wr2l, bufA, bufB, N, 256, 1024);
    node_attn_kernel<4, 64, 4, true, true><<<dim3((N + 7) / 8, 1), 256>>>(
        bufA, bufB, ea, We2, att2, b2, ptr, eid, esrc, bufD, N);

    // ===== Layer 3: conv A (K=256, KT=16) + GEMM + attention (master edges) =====
    convA_kernel<<<RB_BLOCKS * 16 * 4, 256>>>(bufD, af, af + ASZ, N, 256, 16);
    gemm_bf16_kernel<<<dim3(3, RB_BLOCKS, 2), 256, GEMM_SMEM>>>(
        af, af + ASZ, wlph, wlpl, wrph, wrpl, bufA, bufB, N, 384, 256);
    node_attn_kernel<6, 64, 6, false, false><<<dim3((N + 7) / 8, 1), 256>>>(
        bufA, bufB, nullptr, nullptr, attp, bp, ptr2, eid2, esrc2, bufC, N);

    // ===== readout + MLP head =====
    last_idx_kernel<<<1, 32>>>(n_nodes, last, N_GRAPHS);
    fc_kernel<<<N_GRAPHS, 64>>>(bufC, last, Wfc1, bfc1, Wfc2, bfc2, (float*)d_out);
}